// round 3
// baseline (speedup 1.0000x reference)
#include <cuda_runtime.h>
#include <cstddef>
#include <cstdint>

#define T_STEPS 2048
#define BATCH   64
#define D_IN    256
#define D_H     256
#define NQ      8
#define ZLD     1032         // 4*256 + 8
#define QSTR    0.5f
#define NCTA    128          // persistent grid: 4 b-tiles x 32 u-tiles

// ---------------- scratch (static device globals; no allocation) ------------
__device__ float g_Z[(size_t)T_STEPS * BATCH * ZLD];   // x-projection + bias
__device__ unsigned long long g_bar_count = 0ull;      // grid barrier (monotonic)

// ---------------------------------------------------------------------------
// Kernel 1: precompute Z = X @ Wx + bias  (x-part rows 0..255 of each W)
// M = T*B = 131072, K = 256, N = 1032 (tiles: 16 gate tiles of 64 + 1 q tile)
// ---------------------------------------------------------------------------
__global__ void xproj_kernel(const float* __restrict__ X,
                             const float* __restrict__ Wf, const float* __restrict__ bf,
                             const float* __restrict__ Wi, const float* __restrict__ bi,
                             const float* __restrict__ Wg, const float* __restrict__ bg,
                             const float* __restrict__ Wo, const float* __restrict__ bo,
                             const float* __restrict__ Wq, const float* __restrict__ bq)
{
    __shared__ float Xs[16][65];   // padded to kill bank conflicts
    __shared__ float Bs[16][64];

    const int row0  = blockIdx.x * 64;
    const int ntile = blockIdx.y;
    const int col0  = ntile * 64;

    const float* W; const float* bias; int ld, wc0, nvalid;
    if (ntile < 4)       { W = Wf; bias = bf; ld = 256; wc0 = col0;       nvalid = 64; }
    else if (ntile < 8)  { W = Wi; bias = bi; ld = 256; wc0 = col0 - 256; nvalid = 64; }
    else if (ntile < 12) { W = Wg; bias = bg; ld = 256; wc0 = col0 - 512; nvalid = 64; }
    else if (ntile < 16) { W = Wo; bias = bo; ld = 256; wc0 = col0 - 768; nvalid = 64; }
    else                 { W = Wq; bias = bq; ld = 8;   wc0 = 0;          nvalid = 8;  }

    const int tid = threadIdx.x;        // 256 threads
    const int tx = tid & 15;            // n direction
    const int ty = tid >> 4;            // m direction

    float acc[4][4] = {};

    for (int k0 = 0; k0 < 256; k0 += 16) {
        #pragma unroll
        for (int l = 0; l < 4; l++) {
            int idx = tid + l * 256;          // 0..1023
            int m = idx >> 4, k = idx & 15;
            Xs[k][m] = X[(size_t)(row0 + m) * 256 + k0 + k];
        }
        #pragma unroll
        for (int l = 0; l < 4; l++) {
            int idx = tid + l * 256;
            int k = idx >> 6, n = idx & 63;
            float v = 0.f;
            if (n < nvalid) v = W[(size_t)(k0 + k) * ld + wc0 + n];
            Bs[k][n] = v;
        }
        __syncthreads();

        #pragma unroll
        for (int kk = 0; kk < 16; kk++) {
            float a[4], b[4];
            #pragma unroll
            for (int i = 0; i < 4; i++) a[i] = Xs[kk][ty * 4 + i];
            #pragma unroll
            for (int j = 0; j < 4; j++) b[j] = Bs[kk][tx * 4 + j];
            #pragma unroll
            for (int i = 0; i < 4; i++)
                #pragma unroll
                for (int j = 0; j < 4; j++)
                    acc[i][j] += a[i] * b[j];
        }
        __syncthreads();
    }

    #pragma unroll
    for (int i = 0; i < 4; i++) {
        int r = row0 + ty * 4 + i;
        #pragma unroll
        for (int j = 0; j < 4; j++) {
            int n = tx * 4 + j;
            if (n < nvalid)
                g_Z[(size_t)r * ZLD + col0 + n] = acc[i][j] + bias[wc0 + n];
        }
    }
}

// ---------------------------------------------------------------------------
// Grid barrier: monotonic counter, replay-safe (count is always a multiple of
// NCTA at kernel start/end). Release fence before arrive; volatile spin.
// ---------------------------------------------------------------------------
__device__ __forceinline__ void grid_barrier()
{
    __syncthreads();
    if (threadIdx.x == 0) {
        __threadfence();
        unsigned long long a = atomicAdd(&g_bar_count, 1ull);
        unsigned long long target = (a / NCTA + 1ull) * NCTA;
        while (*(volatile unsigned long long*)&g_bar_count < target)
            __nanosleep(32);
    }
    __syncthreads();
}

__device__ __forceinline__ float sigmoidf_(float x) {
    return 1.f / (1.f + __expf(-x));
}

// ---------------------------------------------------------------------------
// Kernel 2: persistent recurrence. One launch for all 2048 steps.
// 128 CTAs x 128 threads. Each thread owns one (b, u) pair: 4 gate dots +
// 1 qubit dot over hx (k=256), weights resident in smem for the whole run,
// cx resident in a register for the whole run. hx flows through `stacked`
// (step t reads stacked[t-1] via __ldcg).
// ---------------------------------------------------------------------------
__global__ void __launch_bounds__(128, 1)
lstm_persistent(const float* __restrict__ Wf,
                const float* __restrict__ Wi,
                const float* __restrict__ Wg,
                const float* __restrict__ Wo,
                const float* __restrict__ Wq,
                float* __restrict__ stacked,   // [T,B,256]
                float* __restrict__ hx_out,    // [B,256]
                float* __restrict__ cx_out)    // [B,256]
{
    extern __shared__ float smem[];
    float* sm_h = smem;                 // [16][260]
    float* sm_w = smem + 16 * 260;      // [5][8][260]  (f,i,g,o,q)

    const int tid = threadIdx.x;        // 128
    const int b0  = blockIdx.x * 16;    // gridDim.x = 4
    const int u0  = blockIdx.y * 8;     // gridDim.y = 32

    // ---- stage weights ONCE: hx-part = rows 256..511 of each W ----
    #pragma unroll
    for (int g = 0; g < 4; g++) {
        const float* Wp = (g == 0) ? Wf : (g == 1) ? Wi : (g == 2) ? Wg : Wo;
        for (int idx = tid; idx < 2048; idx += 128) {
            int uu = idx & 7, k = idx >> 3;
            sm_w[(g * 8 + uu) * 260 + k] = Wp[(size_t)(256 + k) * 256 + u0 + uu];
        }
    }
    for (int idx = tid; idx < 2048; idx += 128) {
        int uu = idx & 7, k = idx >> 3;
        sm_w[(4 * 8 + uu) * 260 + k] = Wq[(size_t)(256 + k) * 8 + uu];
    }

    const int bl = tid >> 3;            // 0..15
    const int uu = tid & 7;             // 0..7  (also qubit index)
    const int b  = b0 + bl;
    const int ug = u0 + uu;

    const float* hp  = sm_h + bl * 260;
    const float* wfp = sm_w + (0 * 8 + uu) * 260;
    const float* wip = sm_w + (1 * 8 + uu) * 260;
    const float* wgp = sm_w + (2 * 8 + uu) * 260;
    const float* wop = sm_w + (3 * 8 + uu) * 260;
    const float* wqp = sm_w + (4 * 8 + uu) * 260;

    const float* zrow = g_Z + (size_t)b * ZLD;   // + t*B*ZLD per step

    float c = 0.f;
    float h = 0.f;

    for (int t = 0; t < T_STEPS; t++) {
        // all writes of step t-1 must be visible before we read hx
        if (t > 0) grid_barrier();
        else       __syncthreads();

        // ---- stage hx tile (stacked[t-1], or zeros at t==0) via L2 ----
        const float4* hsrc = (const float4*)(stacked + ((size_t)(t - 1) * BATCH + b0) * 256);
        for (int idx = tid; idx < 1024; idx += 128) {   // 16 b x 64 float4
            int bl2 = idx >> 6, k4 = idx & 63;
            float4 v;
            if (t == 0) { v.x = v.y = v.z = v.w = 0.f; }
            else        { v = __ldcg(hsrc + (size_t)bl2 * 64 + k4); }
            *(float4*)(sm_h + bl2 * 260 + k4 * 4) = v;
        }
        __syncthreads();

        // ---- 5 dot products over k=256 ----
        float aF = 0.f, aI = 0.f, aG = 0.f, aO = 0.f, aQ = 0.f;
        #pragma unroll 8
        for (int k = 0; k < 256; k += 4) {
            float4 h4 = *(const float4*)(hp + k);
            float4 f4 = *(const float4*)(wfp + k);
            float4 i4 = *(const float4*)(wip + k);
            float4 g4 = *(const float4*)(wgp + k);
            float4 o4 = *(const float4*)(wop + k);
            float4 q4 = *(const float4*)(wqp + k);
            aF += h4.x * f4.x + h4.y * f4.y + h4.z * f4.z + h4.w * f4.w;
            aI += h4.x * i4.x + h4.y * i4.y + h4.z * i4.z + h4.w * i4.w;
            aG += h4.x * g4.x + h4.y * g4.y + h4.z * g4.z + h4.w * g4.w;
            aO += h4.x * o4.x + h4.y * o4.y + h4.z * o4.z + h4.w * o4.w;
            aQ += h4.x * q4.x + h4.y * q4.y + h4.z * q4.z + h4.w * q4.w;
        }

        const float* z = zrow + (size_t)t * BATCH * ZLD;
        aF += z[ug];
        aI += z[256 + ug];
        aG += z[512 + ug];
        aO += z[768 + ug];
        aQ += z[1024 + uu];

        // qubit blend: sum of tanh over the 8 qubits of this batch row
        float s = tanhf(aQ);
        s += __shfl_xor_sync(0xffffffffu, s, 1);
        s += __shfl_xor_sync(0xffffffffu, s, 2);
        s += __shfl_xor_sync(0xffffffffu, s, 4);
        const float qout = sigmoidf_(s);

        const float f = (1.f - QSTR) * sigmoidf_(aF) + QSTR * qout;
        const float i = sigmoidf_(aI);
        const float g = tanhf(aG);
        const float o = sigmoidf_(aO);

        c = f * c + i * g;
        h = o * tanhf(c);

        stacked[((size_t)t * BATCH + b) * 256 + ug] = h;
    }

    hx_out[b * 256 + ug] = h;
    cx_out[b * 256 + ug] = c;
}

// ---------------------------------------------------------------------------
extern "C" void kernel_launch(void* const* d_in, const int* in_sizes, int n_in,
                              void* d_out, int out_size)
{
    const float* X  = (const float*)d_in[0];
    const float* Wf = (const float*)d_in[1];
    const float* bf = (const float*)d_in[2];
    const float* Wi = (const float*)d_in[3];
    const float* bi = (const float*)d_in[4];
    const float* Wg = (const float*)d_in[5];
    const float* bg = (const float*)d_in[6];
    const float* Wo = (const float*)d_in[7];
    const float* bo = (const float*)d_in[8];
    const float* Wq = (const float*)d_in[9];
    const float* bq = (const float*)d_in[10];

    float* out     = (float*)d_out;
    float* stacked = out;                                    // [T,B,256]
    float* hx_out  = out + (size_t)T_STEPS * BATCH * D_H;    // [B,256]
    float* cx_out  = hx_out + BATCH * D_H;                   // [B,256]

    // 1) precompute input projections (parallel GEMM)
    dim3 g1(T_STEPS * BATCH / 64, 17);
    xproj_kernel<<<g1, 256>>>(X, Wf, bf, Wi, bi, Wg, bg, Wo, bo, Wq, bq);

    // 2) persistent recurrence (single launch, grid barrier per step)
    const int smem_bytes = (16 * 260 + 5 * 8 * 260) * sizeof(float);  // 58240
    static int attr_set = 0;
    cudaFuncSetAttribute(lstm_persistent,
                         cudaFuncAttributeMaxDynamicSharedMemorySize, smem_bytes);
    (void)attr_set;
    dim3 g2(4, 32);
    lstm_persistent<<<g2, 128, smem_bytes>>>(Wf, Wi, Wg, Wo, Wq,
                                             stacked, hx_out, cx_out);
}

// round 4
// speedup vs baseline: 1.0736x; 1.0736x over previous
#include <cuda_runtime.h>
#include <cstddef>
#include <cstdint>

#define T_STEPS 2048
#define BATCH   64
#define D_IN    256
#define D_H     256
#define NQ      8
#define ZLD     1032         // 4*256 + 8
#define QSTR    0.5f
#define NCTA    128          // persistent grid: 4 b-tiles x 32 u-tiles

// ---------------- scratch (static device globals; no allocation) ------------
__device__ float g_Z[(size_t)T_STEPS * BATCH * ZLD];   // x-projection + bias
__device__ unsigned long long g_bar_count = 0ull;      // grid barrier (monotonic)

// ---------------------------------------------------------------------------
// Kernel 1: precompute Z = X @ Wx + bias  (x-part rows 0..255 of each W)
// ---------------------------------------------------------------------------
__global__ void xproj_kernel(const float* __restrict__ X,
                             const float* __restrict__ Wf, const float* __restrict__ bf,
                             const float* __restrict__ Wi, const float* __restrict__ bi,
                             const float* __restrict__ Wg, const float* __restrict__ bg,
                             const float* __restrict__ Wo, const float* __restrict__ bo,
                             const float* __restrict__ Wq, const float* __restrict__ bq)
{
    __shared__ float Xs[16][65];
    __shared__ float Bs[16][64];

    const int row0  = blockIdx.x * 64;
    const int ntile = blockIdx.y;
    const int col0  = ntile * 64;

    const float* W; const float* bias; int ld, wc0, nvalid;
    if (ntile < 4)       { W = Wf; bias = bf; ld = 256; wc0 = col0;       nvalid = 64; }
    else if (ntile < 8)  { W = Wi; bias = bi; ld = 256; wc0 = col0 - 256; nvalid = 64; }
    else if (ntile < 12) { W = Wg; bias = bg; ld = 256; wc0 = col0 - 512; nvalid = 64; }
    else if (ntile < 16) { W = Wo; bias = bo; ld = 256; wc0 = col0 - 768; nvalid = 64; }
    else                 { W = Wq; bias = bq; ld = 8;   wc0 = 0;          nvalid = 8;  }

    const int tid = threadIdx.x;        // 256 threads
    const int tx = tid & 15;
    const int ty = tid >> 4;

    float acc[4][4] = {};

    for (int k0 = 0; k0 < 256; k0 += 16) {
        #pragma unroll
        for (int l = 0; l < 4; l++) {
            int idx = tid + l * 256;
            int m = idx >> 4, k = idx & 15;
            Xs[k][m] = X[(size_t)(row0 + m) * 256 + k0 + k];
        }
        #pragma unroll
        for (int l = 0; l < 4; l++) {
            int idx = tid + l * 256;
            int k = idx >> 6, n = idx & 63;
            float v = 0.f;
            if (n < nvalid) v = W[(size_t)(k0 + k) * ld + wc0 + n];
            Bs[k][n] = v;
        }
        __syncthreads();

        #pragma unroll
        for (int kk = 0; kk < 16; kk++) {
            float a[4], b[4];
            #pragma unroll
            for (int i = 0; i < 4; i++) a[i] = Xs[kk][ty * 4 + i];
            #pragma unroll
            for (int j = 0; j < 4; j++) b[j] = Bs[kk][tx * 4 + j];
            #pragma unroll
            for (int i = 0; i < 4; i++)
                #pragma unroll
                for (int j = 0; j < 4; j++)
                    acc[i][j] += a[i] * b[j];
        }
        __syncthreads();
    }

    #pragma unroll
    for (int i = 0; i < 4; i++) {
        int r = row0 + ty * 4 + i;
        #pragma unroll
        for (int j = 0; j < 4; j++) {
            int n = tx * 4 + j;
            if (n < nvalid)
                g_Z[(size_t)r * ZLD + col0 + n] = acc[i][j] + bias[wc0 + n];
        }
    }
}

// ---------------------------------------------------------------------------
// Grid barrier: all threads fence (stores drained to L2), thread0 arrives and
// spins on a monotonic counter (replay-safe: multiple of NCTA at launch edges).
// ---------------------------------------------------------------------------
__device__ __forceinline__ void grid_barrier()
{
    __threadfence();
    __syncthreads();
    if (threadIdx.x == 0) {
        unsigned long long a = atomicAdd(&g_bar_count, 1ull);
        unsigned long long target = (a / NCTA + 1ull) * NCTA;
        while (*(volatile unsigned long long*)&g_bar_count < target)
            __nanosleep(32);
    }
    __syncthreads();
}

__device__ __forceinline__ float sigmoidf_(float x) {
    return 1.f / (1.f + __expf(-x));
}

// ---------------------------------------------------------------------------
// Kernel 2: persistent recurrence, 128 CTAs x 512 threads.
// Each CTA: 16 batch rows x 8 units. Warp = one batch row; lane = kc*8+uu
// (kc = k-chunk 0..3 of 64, uu = unit/qubit 0..7). Partial dots reduced via
// shfl_xor(8,16). Weights resident in smem for all 2048 steps; cx in register.
// ---------------------------------------------------------------------------
__global__ void __launch_bounds__(512, 1)
lstm_persistent(const float* __restrict__ Wf,
                const float* __restrict__ Wi,
                const float* __restrict__ Wg,
                const float* __restrict__ Wo,
                const float* __restrict__ Wq,
                float* __restrict__ stacked,   // [T,B,256]
                float* __restrict__ hx_out,    // [B,256]
                float* __restrict__ cx_out)    // [B,256]
{
    extern __shared__ float smem[];
    float* sm_h = smem;                 // [16][260]
    float* sm_w = smem + 16 * 260;      // [5][8][260]  (f,i,g,o,q)

    const int tid = threadIdx.x;        // 512
    const int b0  = blockIdx.x * 16;    // gridDim.x = 4
    const int u0  = blockIdx.y * 8;     // gridDim.y = 32

    // ---- stage weights ONCE: hx-part = rows 256..511 of each W ----
    #pragma unroll
    for (int g = 0; g < 4; g++) {
        const float* Wp = (g == 0) ? Wf : (g == 1) ? Wi : (g == 2) ? Wg : Wo;
        for (int idx = tid; idx < 2048; idx += 512) {
            int uu = idx & 7, k = idx >> 3;
            sm_w[(g * 8 + uu) * 260 + k] = Wp[(size_t)(256 + k) * 256 + u0 + uu];
        }
    }
    for (int idx = tid; idx < 2048; idx += 512) {
        int uu = idx & 7, k = idx >> 3;
        sm_w[(4 * 8 + uu) * 260 + k] = Wq[(size_t)(256 + k) * 8 + uu];
    }

    const int bl   = tid >> 5;          // 0..15 (warp id = batch row)
    const int lane = tid & 31;
    const int kc   = lane >> 3;         // 0..3  k-chunk
    const int uu   = lane & 7;          // 0..7  unit / qubit index
    const int b    = b0 + bl;
    const int ug   = u0 + uu;

    const int ko = kc * 64;
    const float* hp  = sm_h + bl * 260 + ko;
    const float* wfp = sm_w + (0 * 8 + uu) * 260 + ko;
    const float* wip = sm_w + (1 * 8 + uu) * 260 + ko;
    const float* wgp = sm_w + (2 * 8 + uu) * 260 + ko;
    const float* wop = sm_w + (3 * 8 + uu) * 260 + ko;
    const float* wqp = sm_w + (4 * 8 + uu) * 260 + ko;

    const float* zrow = g_Z + (size_t)b * ZLD;   // + t*B*ZLD per step
    float* srow = stacked + (size_t)b * 256 + ug;

    float c = 0.f;
    float h = 0.f;

    for (int t = 0; t < T_STEPS; t++) {
        // prefetch Z for this step (independent of recurrence) before barrier
        const float* z = zrow + (size_t)t * BATCH * ZLD;
        const float zF = __ldg(z + ug);
        const float zI = __ldg(z + 256 + ug);
        const float zG = __ldg(z + 512 + ug);
        const float zO = __ldg(z + 768 + ug);
        const float zQ = __ldg(z + 1024 + uu);

        // writes of step t-1 must be visible before reading hx
        if (t > 0) grid_barrier();
        else       __syncthreads();

        // ---- stage hx tile (stacked[t-1], or zeros at t==0) via L2 ----
        const float4* hsrc = (const float4*)(stacked + ((size_t)(t - 1) * BATCH + b0) * 256);
        #pragma unroll
        for (int i = 0; i < 2; i++) {
            int idx = tid + i * 512;            // 0..1023
            int bl2 = idx >> 6, k4 = idx & 63;
            float4 v;
            if (t == 0) { v.x = v.y = v.z = v.w = 0.f; }
            else        { v = __ldcg(hsrc + (size_t)bl2 * 64 + k4); }
            *(float4*)(sm_h + bl2 * 260 + k4 * 4) = v;
        }
        __syncthreads();

        // ---- partial dot products over this thread's 64-element k chunk ----
        float aF = 0.f, aI = 0.f, aG = 0.f, aO = 0.f, aQ = 0.f;
        #pragma unroll
        for (int k = 0; k < 64; k += 4) {
            float4 h4 = *(const float4*)(hp + k);
            float4 f4 = *(const float4*)(wfp + k);
            float4 i4 = *(const float4*)(wip + k);
            float4 g4 = *(const float4*)(wgp + k);
            float4 o4 = *(const float4*)(wop + k);
            float4 q4 = *(const float4*)(wqp + k);
            aF += h4.x * f4.x + h4.y * f4.y + h4.z * f4.z + h4.w * f4.w;
            aI += h4.x * i4.x + h4.y * i4.y + h4.z * i4.z + h4.w * i4.w;
            aG += h4.x * g4.x + h4.y * g4.y + h4.z * g4.z + h4.w * g4.w;
            aO += h4.x * o4.x + h4.y * o4.y + h4.z * o4.z + h4.w * o4.w;
            aQ += h4.x * q4.x + h4.y * q4.y + h4.z * q4.z + h4.w * q4.w;
        }

        // ---- reduce across the 4 k-chunks (lane bits 3,4) ----
        aF += __shfl_xor_sync(0xffffffffu, aF, 8);
        aF += __shfl_xor_sync(0xffffffffu, aF, 16);
        aI += __shfl_xor_sync(0xffffffffu, aI, 8);
        aI += __shfl_xor_sync(0xffffffffu, aI, 16);
        aG += __shfl_xor_sync(0xffffffffu, aG, 8);
        aG += __shfl_xor_sync(0xffffffffu, aG, 16);
        aO += __shfl_xor_sync(0xffffffffu, aO, 8);
        aO += __shfl_xor_sync(0xffffffffu, aO, 16);
        aQ += __shfl_xor_sync(0xffffffffu, aQ, 8);
        aQ += __shfl_xor_sync(0xffffffffu, aQ, 16);

        aF += zF; aI += zI; aG += zG; aO += zO; aQ += zQ;

        // qubit blend: sum of tanh over the 8 qubits of this batch row
        float s = tanhf(aQ);
        s += __shfl_xor_sync(0xffffffffu, s, 1);
        s += __shfl_xor_sync(0xffffffffu, s, 2);
        s += __shfl_xor_sync(0xffffffffu, s, 4);
        const float qout = sigmoidf_(s);

        const float f = (1.f - QSTR) * sigmoidf_(aF) + QSTR * qout;
        const float i = sigmoidf_(aI);
        const float g = tanhf(aG);
        const float o = sigmoidf_(aO);

        c = f * c + i * g;
        h = o * tanhf(c);

        if (kc == 0)
            __stcg(srow + (size_t)t * BATCH * 256, h);
    }

    if (kc == 0) {
        hx_out[b * 256 + ug] = h;
        cx_out[b * 256 + ug] = c;
    }
}

// ---------------------------------------------------------------------------
extern "C" void kernel_launch(void* const* d_in, const int* in_sizes, int n_in,
                              void* d_out, int out_size)
{
    const float* X  = (const float*)d_in[0];
    const float* Wf = (const float*)d_in[1];
    const float* bf = (const float*)d_in[2];
    const float* Wi = (const float*)d_in[3];
    const float* bi = (const float*)d_in[4];
    const float* Wg = (const float*)d_in[5];
    const float* bg = (const float*)d_in[6];
    const float* Wo = (const float*)d_in[7];
    const float* bo = (const float*)d_in[8];
    const float* Wq = (const float*)d_in[9];
    const float* bq = (const float*)d_in[10];

    float* out     = (float*)d_out;
    float* stacked = out;                                    // [T,B,256]
    float* hx_out  = out + (size_t)T_STEPS * BATCH * D_H;    // [B,256]
    float* cx_out  = hx_out + BATCH * D_H;                   // [B,256]

    // 1) precompute input projections (parallel GEMM)
    dim3 g1(T_STEPS * BATCH / 64, 17);
    xproj_kernel<<<g1, 256>>>(X, Wf, bf, Wi, bi, Wg, bg, Wo, bo, Wq, bq);

    // 2) persistent recurrence (single launch, grid barrier per step)
    const int smem_bytes = (16 * 260 + 5 * 8 * 260) * sizeof(float);  // 58240
    cudaFuncSetAttribute(lstm_persistent,
                         cudaFuncAttributeMaxDynamicSharedMemorySize, smem_bytes);
    dim3 g2(4, 32);
    lstm_persistent<<<g2, 512, smem_bytes>>>(Wf, Wi, Wg, Wo, Wq,
                                             stacked, hx_out, cx_out);
}

// round 5
// speedup vs baseline: 1.5139x; 1.4101x over previous
#include <cuda_runtime.h>
#include <cstddef>
#include <cstdint>

#define T_STEPS 2048
#define BATCH   64
#define D_IN    256
#define D_H     256
#define NQ      8
#define ZLD     1032         // 4*256 + 8
#define QSTR    0.5f
#define NCTA_PER_GROUP 32    // one barrier group per b-tile (32 u-tiles)

// ---------------- scratch (static device globals; no allocation) ------------
__device__ float g_Z[(size_t)T_STEPS * BATCH * ZLD];        // x-projection + bias
__device__ unsigned long long g_bar[4 * 16];                // 4 groups, 128B apart

// ---------------------------------------------------------------------------
// Kernel 1: precompute Z = X @ Wx + bias  (x-part rows 0..255 of each W)
// ---------------------------------------------------------------------------
__global__ void xproj_kernel(const float* __restrict__ X,
                             const float* __restrict__ Wf, const float* __restrict__ bf,
                             const float* __restrict__ Wi, const float* __restrict__ bi,
                             const float* __restrict__ Wg, const float* __restrict__ bg,
                             const float* __restrict__ Wo, const float* __restrict__ bo,
                             const float* __restrict__ Wq, const float* __restrict__ bq)
{
    __shared__ float Xs[16][65];
    __shared__ float Bs[16][64];

    const int row0  = blockIdx.x * 64;
    const int ntile = blockIdx.y;
    const int col0  = ntile * 64;

    const float* W; const float* bias; int ld, wc0, nvalid;
    if (ntile < 4)       { W = Wf; bias = bf; ld = 256; wc0 = col0;       nvalid = 64; }
    else if (ntile < 8)  { W = Wi; bias = bi; ld = 256; wc0 = col0 - 256; nvalid = 64; }
    else if (ntile < 12) { W = Wg; bias = bg; ld = 256; wc0 = col0 - 512; nvalid = 64; }
    else if (ntile < 16) { W = Wo; bias = bo; ld = 256; wc0 = col0 - 768; nvalid = 64; }
    else                 { W = Wq; bias = bq; ld = 8;   wc0 = 0;          nvalid = 8;  }

    const int tid = threadIdx.x;        // 256 threads
    const int tx = tid & 15;
    const int ty = tid >> 4;

    float acc[4][4] = {};

    for (int k0 = 0; k0 < 256; k0 += 16) {
        #pragma unroll
        for (int l = 0; l < 4; l++) {
            int idx = tid + l * 256;
            int m = idx >> 4, k = idx & 15;
            Xs[k][m] = X[(size_t)(row0 + m) * 256 + k0 + k];
        }
        #pragma unroll
        for (int l = 0; l < 4; l++) {
            int idx = tid + l * 256;
            int k = idx >> 6, n = idx & 63;
            float v = 0.f;
            if (n < nvalid) v = W[(size_t)(k0 + k) * ld + wc0 + n];
            Bs[k][n] = v;
        }
        __syncthreads();

        #pragma unroll
        for (int kk = 0; kk < 16; kk++) {
            float a[4], b[4];
            #pragma unroll
            for (int i = 0; i < 4; i++) a[i] = Xs[kk][ty * 4 + i];
            #pragma unroll
            for (int j = 0; j < 4; j++) b[j] = Bs[kk][tx * 4 + j];
            #pragma unroll
            for (int i = 0; i < 4; i++)
                #pragma unroll
                for (int j = 0; j < 4; j++)
                    acc[i][j] += a[i] * b[j];
        }
        __syncthreads();
    }

    #pragma unroll
    for (int i = 0; i < 4; i++) {
        int r = row0 + ty * 4 + i;
        #pragma unroll
        for (int j = 0; j < 4; j++) {
            int n = tx * 4 + j;
            if (n < nvalid)
                g_Z[(size_t)r * ZLD + col0 + n] = acc[i][j] + bias[wc0 + n];
        }
    }
}

// ---------------------------------------------------------------------------
// packed fp32x2 helpers
// ---------------------------------------------------------------------------
__device__ __forceinline__ unsigned long long pack2(float a, float b) {
    unsigned long long r;
    asm("mov.b64 %0, {%1, %2};" : "=l"(r) : "f"(a), "f"(b));
    return r;
}
__device__ __forceinline__ void unpack2(unsigned long long v, float& a, float& b) {
    asm("mov.b64 {%0, %1}, %2;" : "=f"(a), "=f"(b) : "l"(v));
}
__device__ __forceinline__ void fma2(unsigned long long& d,
                                     unsigned long long a, unsigned long long b) {
    asm("fma.rn.f32x2 %0, %1, %2, %0;" : "+l"(d) : "l"(a), "l"(b));
}

__device__ __forceinline__ float sigmoidf_(float x) {
    return 1.f / (1.f + __expf(-x));
}

// grid barrier over the 32 CTAs of one b-tile group
__device__ __forceinline__ void group_barrier(int grp)
{
    __threadfence();
    __syncthreads();
    if (threadIdx.x == 0) {
        unsigned long long* ctr = &g_bar[grp * 16];
        unsigned long long a = atomicAdd(ctr, 1ull);
        unsigned long long target = (a / NCTA_PER_GROUP + 1ull) * NCTA_PER_GROUP;
        while (*(volatile unsigned long long*)ctr < target)
            __nanosleep(16);
    }
    __syncthreads();
}

// ---------------------------------------------------------------------------
// Kernel 2: persistent recurrence, 128 CTAs (4 b-tiles x 32 u-tiles), 256 thr.
// Thread = (uu 0..7, kc 0..15 [16-k chunk], rh 0..1 [8 rows]). Weights for the
// thread's (uu, kc) slice live in REGISTERS for all 2048 steps (80 floats =
// 40 packed f32x2). Per step: stage hx to smem, packed FFMA2 dots, shfl+smem
// reduce over kc, 128 owner threads finalize gates (c kept in registers).
// ---------------------------------------------------------------------------
__global__ void __launch_bounds__(256, 1)
lstm_persistent(const float* __restrict__ Wf,
                const float* __restrict__ Wi,
                const float* __restrict__ Wg,
                const float* __restrict__ Wo,
                const float* __restrict__ Wq,
                float* __restrict__ stacked,   // [T,B,256]
                float* __restrict__ hx_out,    // [B,256]
                float* __restrict__ cx_out)    // [B,256]
{
    __shared__ float sm_h[16 * 264];       // hx tile, padded rows
    __shared__ float sm_red[8 * 320];      // per-warp partials: [warp][uu][40]

    const int tid  = threadIdx.x;          // 256
    const int b0   = blockIdx.x * 16;      // b-tile (barrier group)
    const int u0   = blockIdx.y * 8;       // u-tile

    const int uu   = tid & 7;              // unit / qubit index
    const int kcl  = (tid >> 3) & 3;       // kc low bits (lane)
    const int warp = tid >> 5;             // 0..7
    const int kch  = warp & 3;             // kc high bits (warp)
    const int rh   = warp >> 2;            // row half: rows rh*8 .. rh*8+7
    const int kc   = kch * 4 + kcl;        // 0..15
    const int k0   = kc * 16;

    // ---- load this thread's weight slice into registers (once) ----
    // wv[g][p]: packed (W[k0+2p], W[k0+2p+1]) for column u0+uu (g<4) / uu (g=4)
    unsigned long long wv[5][8];
    {
        const float* Wp[4] = { Wf, Wi, Wg, Wo };
        #pragma unroll
        for (int g = 0; g < 4; g++) {
            #pragma unroll
            for (int p = 0; p < 8; p++) {
                int k = 256 + k0 + 2 * p;
                float w0 = Wp[g][(size_t)k * 256 + u0 + uu];
                float w1 = Wp[g][(size_t)(k + 1) * 256 + u0 + uu];
                wv[g][p] = pack2(w0, w1);
            }
        }
        #pragma unroll
        for (int p = 0; p < 8; p++) {
            int k = 256 + k0 + 2 * p;
            wv[4][p] = pack2(Wq[(size_t)k * 8 + uu], Wq[(size_t)(k + 1) * 8 + uu]);
        }
    }

    // ---- owner thread mapping (tid < 128): one (row, unit) output each ----
    const int o_row = tid >> 3;            // 0..15 (valid when tid<128)
    const int o_uu  = tid & 7;
    const int ob    = b0 + o_row;
    const int oug   = u0 + o_uu;
    const float* o_z = g_Z + (size_t)ob * ZLD;
    float c = 0.f, h = 0.f;

    for (int t = 0; t < T_STEPS; t++) {
        // prefetch Z for this step (owners only; independent of recurrence)
        float zF = 0.f, zI = 0.f, zG = 0.f, zO = 0.f, zQ = 0.f;
        if (tid < 128) {
            const float* z = o_z + (size_t)t * BATCH * ZLD;
            zF = __ldg(z + oug);
            zI = __ldg(z + 256 + oug);
            zG = __ldg(z + 512 + oug);
            zO = __ldg(z + 768 + oug);
            zQ = __ldg(z + 1024 + o_uu);
        }

        // writes of step t-1 (within this b-tile group) visible before reads
        if (t > 0) group_barrier(blockIdx.x);

        // ---- stage hx tile (stacked[t-1], zeros at t==0) ----
        const float4* hsrc = (const float4*)(stacked + ((size_t)(t - 1) * BATCH + b0) * 256);
        #pragma unroll
        for (int i = 0; i < 4; i++) {
            int idx = tid + i * 256;                // 0..1023
            int row = idx >> 6, k4 = idx & 63;
            float4 v;
            if (t == 0) { v.x = v.y = v.z = v.w = 0.f; }
            else        { v = __ldcg(hsrc + (size_t)row * 64 + k4); }
            *(float4*)(sm_h + row * 264 + k4 * 4) = v;
        }
        __syncthreads();

        // ---- packed partial dots: 8 rows x 5 gates over 16-k chunk ----
        unsigned long long acc[8][5];
        #pragma unroll
        for (int r = 0; r < 8; r++)
            #pragma unroll
            for (int g = 0; g < 5; g++)
                acc[r][g] = 0ull;

        #pragma unroll
        for (int r = 0; r < 8; r++) {
            const float* hrow = sm_h + (rh * 8 + r) * 264 + k0;
            #pragma unroll
            for (int p4 = 0; p4 < 4; p4++) {
                float4 hv = *(const float4*)(hrow + p4 * 4);
                unsigned long long h01 = pack2(hv.x, hv.y);
                unsigned long long h23 = pack2(hv.z, hv.w);
                #pragma unroll
                for (int g = 0; g < 5; g++) {
                    fma2(acc[r][g], h01, wv[g][2 * p4]);
                    fma2(acc[r][g], h23, wv[g][2 * p4 + 1]);
                }
            }
        }

        // ---- horizontal add + in-warp reduce over kcl (lane bits 3,4) ----
        float v[40];
        #pragma unroll
        for (int r = 0; r < 8; r++)
            #pragma unroll
            for (int g = 0; g < 5; g++) {
                float a, b2;
                unpack2(acc[r][g], a, b2);
                v[r * 5 + g] = a + b2;
            }
        #pragma unroll
        for (int j = 0; j < 40; j++) {
            v[j] += __shfl_xor_sync(0xffffffffu, v[j], 8);
            v[j] += __shfl_xor_sync(0xffffffffu, v[j], 16);
        }

        // ---- cross-warp reduce over kch via smem ----
        if (kcl == 0) {
            float* dst = sm_red + warp * 320 + uu * 40;
            #pragma unroll
            for (int j = 0; j < 40; j++) dst[j] = v[j];
        }
        __syncthreads();

        // ---- owners finalize ----
        if (tid < 128) {
            const int rh_o = o_row >> 3;
            const int rr_o = o_row & 7;
            float aF = zF, aI = zI, aG = zG, aO = zO, aQ = zQ;
            #pragma unroll
            for (int w = 0; w < 4; w++) {
                const float* src = sm_red + (rh_o * 4 + w) * 320 + o_uu * 40 + rr_o * 5;
                aF += src[0];
                aI += src[1];
                aG += src[2];
                aO += src[3];
                aQ += src[4];
            }

            // qubit blend: sum tanh over the 8 qubits of this batch row
            float s = tanhf(aQ);
            s += __shfl_xor_sync(0xffffffffu, s, 1);
            s += __shfl_xor_sync(0xffffffffu, s, 2);
            s += __shfl_xor_sync(0xffffffffu, s, 4);
            const float qout = sigmoidf_(s);

            const float f = (1.f - QSTR) * sigmoidf_(aF) + QSTR * qout;
            const float i = sigmoidf_(aI);
            const float g = tanhf(aG);
            const float o = sigmoidf_(aO);

            c = f * c + i * g;
            h = o * tanhf(c);

            __stcg(stacked + ((size_t)t * BATCH + ob) * 256 + oug, h);
        }
        __syncthreads();   // sm_red / sm_h safe to reuse next step
    }

    if (tid < 128) {
        hx_out[ob * 256 + oug] = h;
        cx_out[ob * 256 + oug] = c;
    }
}

// ---------------------------------------------------------------------------
extern "C" void kernel_launch(void* const* d_in, const int* in_sizes, int n_in,
                              void* d_out, int out_size)
{
    const float* X  = (const float*)d_in[0];
    const float* Wf = (const float*)d_in[1];
    const float* bf = (const float*)d_in[2];
    const float* Wi = (const float*)d_in[3];
    const float* bi = (const float*)d_in[4];
    const float* Wg = (const float*)d_in[5];
    const float* bg = (const float*)d_in[6];
    const float* Wo = (const float*)d_in[7];
    const float* bo = (const float*)d_in[8];
    const float* Wq = (const float*)d_in[9];
    const float* bq = (const float*)d_in[10];

    float* out     = (float*)d_out;
    float* stacked = out;                                    // [T,B,256]
    float* hx_out  = out + (size_t)T_STEPS * BATCH * D_H;    // [B,256]
    float* cx_out  = hx_out + BATCH * D_H;                   // [B,256]

    // 1) precompute input projections (parallel GEMM)
    dim3 g1(T_STEPS * BATCH / 64, 17);
    xproj_kernel<<<g1, 256>>>(X, Wf, bf, Wi, bi, Wg, bg, Wo, bo, Wq, bq);

    // 2) persistent recurrence (single launch, per-b-tile grid barriers)
    dim3 g2(4, 32);
    lstm_persistent<<<g2, 256>>>(Wf, Wi, Wg, Wo, Wq, stacked, hx_out, cx_out);
}

// round 6
// speedup vs baseline: 1.5484x; 1.0228x over previous
#include <cuda_runtime.h>
#include <cstddef>
#include <cstdint>

#define T_STEPS 2048
#define BATCH   64
#define D_IN    256
#define D_H     256
#define NQ      8
#define ZLD     1032         // 4*256 + 8
#define QSTR    0.5f
#define GRP_CTAS 32          // CTAs per barrier group (one b-tile)

// ---------------- scratch (static device globals; no allocation) ------------
__device__ float g_Z[(size_t)T_STEPS * BATCH * ZLD];   // x-projection + bias
__device__ unsigned long long g_ctr[4 * 16];           // per-group monotonic ctr

// ---------------------------------------------------------------------------
// Kernel 1: Z = X @ Wx + bias. Tiles 128m x 64n, 256 threads, 8x4 microtile.
// ---------------------------------------------------------------------------
__global__ void __launch_bounds__(256)
xproj_kernel(const float* __restrict__ X,
             const float* __restrict__ Wf, const float* __restrict__ bf,
             const float* __restrict__ Wi, const float* __restrict__ bi,
             const float* __restrict__ Wg, const float* __restrict__ bg,
             const float* __restrict__ Wo, const float* __restrict__ bo,
             const float* __restrict__ Wq, const float* __restrict__ bq)
{
    __shared__ float Xs[16][132];   // [k][m], padded
    __shared__ float Bs[16][68];    // [k][n], padded

    const int row0  = blockIdx.x * 128;
    const int ntile = blockIdx.y;
    const int col0  = ntile * 64;

    const float* W; const float* bias; int ld, wc0, nvalid;
    if (ntile < 4)       { W = Wf; bias = bf; ld = 256; wc0 = col0;       nvalid = 64; }
    else if (ntile < 8)  { W = Wi; bias = bi; ld = 256; wc0 = col0 - 256; nvalid = 64; }
    else if (ntile < 12) { W = Wg; bias = bg; ld = 256; wc0 = col0 - 512; nvalid = 64; }
    else if (ntile < 16) { W = Wo; bias = bo; ld = 256; wc0 = col0 - 768; nvalid = 64; }
    else                 { W = Wq; bias = bq; ld = 8;   wc0 = 0;          nvalid = 8;  }

    const int tid = threadIdx.x;        // 256
    const int tx  = tid & 15;           // n/4
    const int ty  = tid >> 4;           // m/8

    float acc[8][4] = {};

    for (int k0 = 0; k0 < 256; k0 += 16) {
        // stage Xs: 128m x 16k; each thread 2 float4 along k
        #pragma unroll
        for (int l = 0; l < 2; l++) {
            int idx = tid + l * 256;        // 0..511
            int m = idx >> 2, kq = idx & 3;
            float4 v = *(const float4*)(X + (size_t)(row0 + m) * 256 + k0 + kq * 4);
            Xs[kq * 4 + 0][m] = v.x;
            Xs[kq * 4 + 1][m] = v.y;
            Xs[kq * 4 + 2][m] = v.z;
            Xs[kq * 4 + 3][m] = v.w;
        }
        // stage Bs: 16k x 64n; each thread 1 float4 along n
        {
            int k = tid >> 4, n4 = tid & 15;
            float4 w = { 0.f, 0.f, 0.f, 0.f };
            if (n4 * 4 < nvalid)
                w = *(const float4*)(W + (size_t)(k0 + k) * ld + wc0 + n4 * 4);
            *(float4*)&Bs[k][n4 * 4] = w;
        }
        __syncthreads();

        #pragma unroll
        for (int kk = 0; kk < 16; kk++) {
            float4 a0 = *(const float4*)&Xs[kk][ty * 8];
            float4 a1 = *(const float4*)&Xs[kk][ty * 8 + 4];
            float4 b  = *(const float4*)&Bs[kk][tx * 4];
            float a[8] = { a0.x, a0.y, a0.z, a0.w, a1.x, a1.y, a1.z, a1.w };
            float bb[4] = { b.x, b.y, b.z, b.w };
            #pragma unroll
            for (int i = 0; i < 8; i++)
                #pragma unroll
                for (int j = 0; j < 4; j++)
                    acc[i][j] += a[i] * bb[j];
        }
        __syncthreads();
    }

    #pragma unroll
    for (int i = 0; i < 8; i++) {
        int r = row0 + ty * 8 + i;
        #pragma unroll
        for (int j = 0; j < 4; j++) {
            int n = tx * 4 + j;
            if (n < nvalid)
                g_Z[(size_t)r * ZLD + col0 + n] = acc[i][j] + bias[wc0 + n];
        }
    }
}

// ---------------------------------------------------------------------------
// packed fp32x2 helpers
// ---------------------------------------------------------------------------
__device__ __forceinline__ unsigned long long pack2(float a, float b) {
    unsigned long long r;
    asm("mov.b64 %0, {%1, %2};" : "=l"(r) : "f"(a), "f"(b));
    return r;
}
__device__ __forceinline__ void unpack2(unsigned long long v, float& a, float& b) {
    asm("mov.b64 {%0, %1}, %2;" : "=f"(a), "=f"(b) : "l"(v));
}
__device__ __forceinline__ void fma2(unsigned long long& d,
                                     unsigned long long a, unsigned long long b) {
    asm("fma.rn.f32x2 %0, %1, %2, %0;" : "+l"(d) : "l"(a), "l"(b));
}

__device__ __forceinline__ float sigmoidf_(float x) {
    return 1.f / (1.f + __expf(-x));
}

__device__ __forceinline__ void red_add_u64(unsigned long long* p) {
    asm volatile("red.global.gpu.add.u64 [%0], %1;" :: "l"(p), "l"(1ull) : "memory");
}
__device__ __forceinline__ unsigned long long ld_vol_u64(const unsigned long long* p) {
    unsigned long long v;
    asm volatile("ld.volatile.global.u64 %0, [%1];" : "=l"(v) : "l"(p));
    return v;
}

// ---------------------------------------------------------------------------
// Kernel 2: persistent recurrence, 128 CTAs (4 b-tiles x 32 u-tiles), 512 thr.
// warp = (kch 0..7, rh 0..1); lane = (uu 0..7, kcl 0..3); kc = kch*4+kcl (8-k
// chunk). Thread: 8 rows x 8k x 5 gates, done in two 4-row passes (register
// pressure). Weights (packed k-pairs) in registers for all 2048 steps; cx in
// owner registers. Per-group monotonic-counter barrier with red.add.
// ---------------------------------------------------------------------------
__global__ void __launch_bounds__(512, 1)
lstm_persistent(const float* __restrict__ Wf,
                const float* __restrict__ Wi,
                const float* __restrict__ Wg,
                const float* __restrict__ Wo,
                const float* __restrict__ Wq,
                float* __restrict__ stacked,   // [T,B,256]
                float* __restrict__ hx_out,    // [B,256]
                float* __restrict__ cx_out)    // [B,256]
{
    __shared__ float sm_h[16 * 264];        // hx tile, padded rows
    __shared__ float sm_red[16 * 352];      // [warp][uu(stride 44)][c2*20+j*5+g]

    const int tid  = threadIdx.x;           // 512
    const int warp = tid >> 5;              // 0..15
    const int lane = tid & 31;
    const int b0   = blockIdx.x * 16;       // b-tile (barrier group)
    const int u0   = blockIdx.y * 8;        // u-tile

    const int uu   = lane & 7;
    const int kcl  = lane >> 3;             // 0..3
    const int kch  = warp & 7;              // 0..7
    const int rh   = warp >> 3;             // 0..1
    const int k0   = (kch * 4 + kcl) * 8;   // 8-k chunk base

    // ---- weights: packed k-pairs, 5 gates x 4 pairs, in registers ----
    unsigned long long wv[5][4];
    {
        const float* Wp[4] = { Wf, Wi, Wg, Wo };
        #pragma unroll
        for (int g = 0; g < 4; g++)
            #pragma unroll
            for (int kp = 0; kp < 4; kp++) {
                int k = 256 + k0 + 2 * kp;
                wv[g][kp] = pack2(Wp[g][(size_t)k * 256 + u0 + uu],
                                  Wp[g][(size_t)(k + 1) * 256 + u0 + uu]);
            }
        #pragma unroll
        for (int kp = 0; kp < 4; kp++) {
            int k = 256 + k0 + 2 * kp;
            wv[4][kp] = pack2(Wq[(size_t)k * 8 + uu], Wq[(size_t)(k + 1) * 8 + uu]);
        }
    }

    // ---- owner mapping: tid < 128 -> one (row, unit) output ----
    const int o_row = tid >> 3;
    const int o_uu  = tid & 7;
    const int ob    = b0 + o_row;
    const int oug   = u0 + o_uu;
    const float* o_z = g_Z + (size_t)ob * ZLD;
    float c = 0.f, h = 0.f;

    unsigned long long* ctr = &g_ctr[blockIdx.x * 16];
    unsigned long long base = 0ull;         // thread0 only

    for (int t = 0; t < T_STEPS; t++) {
        // prefetch Z (independent of recurrence) before the wait
        float zF = 0.f, zI = 0.f, zG = 0.f, zO = 0.f, zQ = 0.f;
        if (tid < 128) {
            const float* z = o_z + (size_t)t * BATCH * ZLD;
            zF = __ldg(z + oug);
            zI = __ldg(z + 256 + oug);
            zG = __ldg(z + 512 + oug);
            zO = __ldg(z + 768 + oug);
            zQ = __ldg(z + 1024 + o_uu);
        }

        // ---- wait for step t-1 of this b-tile group ----
        if (t > 0) {
            if (tid == 0) {
                unsigned long long target = base + (unsigned long long)t * GRP_CTAS;
                while (ld_vol_u64(ctr) < target)
                    __nanosleep(16);
            }
            __syncthreads();
        }

        // ---- stage hx tile (stacked[t-1], zeros at t==0) ----
        const float4* hsrc = (const float4*)(stacked + ((size_t)(t - 1) * BATCH + b0) * 256);
        #pragma unroll
        for (int i = 0; i < 2; i++) {
            int idx = tid + i * 512;            // 0..1023
            int row = idx >> 6, k4 = idx & 63;
            float4 v;
            if (t == 0) { v.x = v.y = v.z = v.w = 0.f; }
            else        { v = __ldcg(hsrc + (size_t)row * 64 + k4); }
            *(float4*)(sm_h + row * 264 + k4 * 4) = v;
        }
        __syncthreads();

        // ---- two 4-row passes: dots + reduce ----
        #pragma unroll
        for (int c2 = 0; c2 < 2; c2++) {
            unsigned long long acc[4][5];
            #pragma unroll
            for (int j = 0; j < 4; j++)
                #pragma unroll
                for (int g = 0; g < 5; g++) acc[j][g] = 0ull;

            #pragma unroll
            for (int j = 0; j < 4; j++) {
                const float* hrow = sm_h + (rh * 8 + c2 * 4 + j) * 264 + k0;
                float4 hv0 = *(const float4*)(hrow);
                float4 hv1 = *(const float4*)(hrow + 4);
                unsigned long long hk0 = pack2(hv0.x, hv0.y);
                unsigned long long hk1 = pack2(hv0.z, hv0.w);
                unsigned long long hk2 = pack2(hv1.x, hv1.y);
                unsigned long long hk3 = pack2(hv1.z, hv1.w);
                #pragma unroll
                for (int g = 0; g < 5; g++) {
                    fma2(acc[j][g], hk0, wv[g][0]);
                    fma2(acc[j][g], hk1, wv[g][1]);
                    fma2(acc[j][g], hk2, wv[g][2]);
                    fma2(acc[j][g], hk3, wv[g][3]);
                }
            }

            // horizontal + reduce over kcl (lane bits 3,4)
            float v[20];
            #pragma unroll
            for (int j = 0; j < 4; j++)
                #pragma unroll
                for (int g = 0; g < 5; g++) {
                    float lo, hi;
                    unpack2(acc[j][g], lo, hi);
                    v[j * 5 + g] = lo + hi;
                }
            #pragma unroll
            for (int m = 0; m < 20; m++) {
                v[m] += __shfl_xor_sync(0xffffffffu, v[m], 8);
                v[m] += __shfl_xor_sync(0xffffffffu, v[m], 16);
            }
            if (kcl == 0) {
                float* dst = sm_red + warp * 352 + uu * 44 + c2 * 20;
                #pragma unroll
                for (int q4 = 0; q4 < 5; q4++)
                    *(float4*)(dst + q4 * 4) = make_float4(v[q4*4], v[q4*4+1],
                                                           v[q4*4+2], v[q4*4+3]);
            }
        }
        __syncthreads();

        // ---- owners finalize ----
        if (tid < 128) {
            const int rh_o = o_row >> 3;
            const int rr   = o_row & 7;
            const int c2_o = rr >> 2;
            const int j_o  = rr & 3;
            float aF = zF, aI = zI, aG = zG, aO = zO, aQ = zQ;
            #pragma unroll
            for (int w2 = 0; w2 < 8; w2++) {
                const float* src = sm_red + (rh_o * 8 + w2) * 352 + o_uu * 44
                                 + c2_o * 20 + j_o * 5;
                aF += src[0]; aI += src[1]; aG += src[2]; aO += src[3]; aQ += src[4];
            }

            float s = tanhf(aQ);
            s += __shfl_xor_sync(0xffffffffu, s, 1);
            s += __shfl_xor_sync(0xffffffffu, s, 2);
            s += __shfl_xor_sync(0xffffffffu, s, 4);
            const float qout = sigmoidf_(s);

            const float f = (1.f - QSTR) * sigmoidf_(aF) + QSTR * qout;
            const float i = sigmoidf_(aI);
            const float g = tanhf(aG);
            const float o = sigmoidf_(aO);

            c = f * c + i * g;
            h = o * tanhf(c);

            __stcg(stacked + ((size_t)t * BATCH + ob) * 256 + oug, h);
            __threadfence();   // h visible before the arrive below
        }
        __syncthreads();

        // ---- arrive ----
        if (tid == 0) {
            if (t == 0) {
                unsigned long long a = atomicAdd(ctr, 1ull);
                base = (a / GRP_CTAS) * GRP_CTAS;   // counter base this launch
            } else {
                red_add_u64(ctr);
            }
        }
    }

    if (tid < 128) {
        hx_out[ob * 256 + oug] = h;
        cx_out[ob * 256 + oug] = c;
    }
}

// ---------------------------------------------------------------------------
extern "C" void kernel_launch(void* const* d_in, const int* in_sizes, int n_in,
                              void* d_out, int out_size)
{
    const float* X  = (const float*)d_in[0];
    const float* Wf = (const float*)d_in[1];
    const float* bf = (const float*)d_in[2];
    const float* Wi = (const float*)d_in[3];
    const float* bi = (const float*)d_in[4];
    const float* Wg = (const float*)d_in[5];
    const float* bg = (const float*)d_in[6];
    const float* Wo = (const float*)d_in[7];
    const float* bo = (const float*)d_in[8];
    const float* Wq = (const float*)d_in[9];
    const float* bq = (const float*)d_in[10];

    float* out     = (float*)d_out;
    float* stacked = out;                                    // [T,B,256]
    float* hx_out  = out + (size_t)T_STEPS * BATCH * D_H;    // [B,256]
    float* cx_out  = hx_out + BATCH * D_H;                   // [B,256]

    // 1) precompute input projections
    dim3 g1(T_STEPS * BATCH / 128, 17);
    xproj_kernel<<<g1, 256>>>(X, Wf, bf, Wi, bi, Wg, bg, Wo, bo, Wq, bq);

    // 2) persistent recurrence
    dim3 g2(4, 32);
    lstm_persistent<<<g2, 512>>>(Wf, Wi, Wg, Wo, Wq, stacked, hx_out, cx_out);
}